// round 3
// baseline (speedup 1.0000x reference)
#include <cuda_runtime.h>
#include <cuda_bf16.h>
#include <stdint.h>

#define NB 2
#define NH 48
#define NW 48
#define ND 24
#define NA 9
#define NK 20
#define TOTAL  497664            // NH*NW*ND*NA
#define HWD    55296             // NH*NW*ND
#define OUTTOT 995328            // NB*NA*HWD
#define NUMFG 128
#define RPNB  256
#define NBINS 65536
#define BPB   243                // blocks per batch in pass A/B (2048 anchors each)

#define OFF_BT  995328
#define OFF_IW  (OFF_BT + 5971968)
#define OFF_OW  (OFF_IW + 5971968)

// ---------------- device scratch (no allocations allowed) ----------------
__device__ float              g_gt[NB * NK * 7];   // x1 y1 x2 y2 z1 z2 area
__device__ int                g_gtmax[NB * NK];    // float-as-int max IoU per gt
__device__ signed char        g_label[NB * TOTAL];
__device__ signed char        g_flabel[NB * TOTAL];
__device__ unsigned char      g_amax[NB * TOTAL];
__device__ int                g_cnt[4];            // [b*2 + isbg] candidate counts
__device__ unsigned int       g_hist[4 * NBINS];
__device__ unsigned long long g_prefix[4];
__device__ int                g_m[4];
__device__ int                g_act[4];
__device__ float              g_wval;

// IoU with strict _rn intrinsics so passA and passB are bitwise identical.
__device__ __forceinline__ float f_ov(float ax1, float ay1, float ax2, float ay2,
                                      float az1, float az2, float aarea,
                                      const float* __restrict__ g) {
    float iw = __fadd_rn(__fsub_rn(fminf(ax2, g[2]), fmaxf(ax1, g[0])), 1.0f);
    if (iw <= 0.0f) return 0.0f;
    float ih = __fadd_rn(__fsub_rn(fminf(ay2, g[3]), fmaxf(ay1, g[1])), 1.0f);
    if (ih <= 0.0f) return 0.0f;
    float idp = __fadd_rn(__fsub_rn(fminf(az2, g[5]), fmaxf(az1, g[4])), 1.0f);
    if (idp <= 0.0f) return 0.0f;
    float inter = __fmul_rn(__fmul_rn(iw, ih), idp);
    float den   = __fsub_rn(__fadd_rn(aarea, g[6]), inter);
    return __fdiv_rn(inter, den);
}

__device__ __forceinline__ float f_area(float x1, float y1, float x2, float y2,
                                        float z1, float z2) {
    float aw = __fadd_rn(__fsub_rn(x2, x1), 1.0f);
    float ah = __fadd_rn(__fsub_rn(y2, y1), 1.0f);
    float ad = __fadd_rn(__fsub_rn(z2, z1), 1.0f);
    return __fmul_rn(__fmul_rn(aw, ah), ad);
}

// ---------------- k_init ----------------
__global__ void k_init(const float* __restrict__ gt) {
    int idx = blockIdx.x * blockDim.x + threadIdx.x;
    if (idx < 4 * NBINS) g_hist[idx] = 0u;
    if (idx < NB * NK) {
        g_gtmax[idx] = __float_as_int(-1.0f);
        const float* g = gt + idx * 7;
        float x1 = g[0], y1 = g[1], x2 = g[2], y2 = g[3], z1 = g[4], z2 = g[5];
        float gw = __fadd_rn(__fsub_rn(x2, x1), 1.0f);
        float gh = __fadd_rn(__fsub_rn(y2, y1), 1.0f);
        float gd = __fadd_rn(__fsub_rn(z2, z1), 1.0f);
        // zero-size gt => force ov = 0 via impossible box
        if (gw == 1.0f && gh == 1.0f && gd == 1.0f) { x2 = -1e9f; }
        float* o = g_gt + idx * 7;
        o[0] = x1; o[1] = y1; o[2] = x2; o[3] = y2; o[4] = z1; o[5] = z2;
        o[6] = __fmul_rn(__fmul_rn(gw, gh), gd);
    }
    if (idx < 4) { g_cnt[idx] = 0; g_prefix[idx] = 0ULL; g_m[idx] = 0; g_act[idx] = 1; }
}

// ---------------- passA: gt_max over inside anchors ----------------
__global__ void __launch_bounds__(256) k_passA(const float* __restrict__ anchors,
                                               const float* __restrict__ im_info) {
    int b    = blockIdx.x / BPB;
    int base = (blockIdx.x % BPB) * 2048;
    __shared__ float sgt[NK * 7];
    __shared__ float sanch[NA * 6];
    __shared__ float red[8][NK];
    for (int j = threadIdx.x; j < NK * 7; j += 256) sgt[j] = g_gt[b * NK * 7 + j];
    if (threadIdx.x < NA * 6) sanch[threadIdx.x] = anchors[threadIdx.x];
    __syncthreads();
    float iH = im_info[0], iW = im_info[1], iD = im_info[2];

    float vmax[NK];
#pragma unroll
    for (int k = 0; k < NK; k++) vmax[k] = -1.0f;

    for (int t = 0; t < 8; t++) {
        int i = base + t * 256 + threadIdx.x;
        int a = i % NA; int q = i / NA;
        int d = q % ND; q /= ND;
        int w = q % NW; int h = q / NW;
        float shx = w * 16.0f, shy = h * 16.0f, shz = d * 16.0f;
        const float* an = sanch + a * 6;
        float ax1 = an[0] + shx, ay1 = an[1] + shy;
        float ax2 = an[2] + shx, ay2 = an[3] + shy;
        float az1 = an[4] + shz, az2 = an[5] + shz;
        bool inside = (ax1 >= 0.0f) && (ay1 >= 0.0f) && (az1 >= 0.0f) &&
                      (ax2 < iW) && (ay2 < iH) && (az2 < iD);
        if (!inside) continue;
        float aarea = f_area(ax1, ay1, ax2, ay2, az1, az2);
#pragma unroll
        for (int k = 0; k < NK; k++) {
            float ov = f_ov(ax1, ay1, ax2, ay2, az1, az2, aarea, sgt + k * 7);
            vmax[k] = fmaxf(vmax[k], ov);
        }
    }
    int lane = threadIdx.x & 31, wid = threadIdx.x >> 5;
#pragma unroll
    for (int k = 0; k < NK; k++) {
        float v = vmax[k];
#pragma unroll
        for (int off = 16; off; off >>= 1) v = fmaxf(v, __shfl_xor_sync(0xFFFFFFFFu, v, off));
        if (lane == 0) red[wid][k] = v;
    }
    __syncthreads();
    if (threadIdx.x < NK) {
        float m = red[0][threadIdx.x];
#pragma unroll
        for (int wq = 1; wq < 8; wq++) m = fmaxf(m, red[wq][threadIdx.x]);
        atomicMax(&g_gtmax[b * NK + threadIdx.x], __float_as_int(m));
    }
}

// ---------------- passB: labels, argmax, hist pass 0, counts ----------------
__global__ void __launch_bounds__(256) k_passB(const float* __restrict__ anchors,
                                               const float* __restrict__ im_info,
                                               const float* __restrict__ rfg,
                                               const float* __restrict__ rbg) {
    int b    = blockIdx.x / BPB;
    int base = (blockIdx.x % BPB) * 2048;
    __shared__ float sgt[NK * 7];
    __shared__ float sgm[NK];
    __shared__ float sanch[NA * 6];
    __shared__ int   scnt[2];
    for (int j = threadIdx.x; j < NK * 7; j += 256) sgt[j] = g_gt[b * NK * 7 + j];
    if (threadIdx.x < NK) {
        float gm = __int_as_float(g_gtmax[b * NK + threadIdx.x]);
        sgm[threadIdx.x] = (gm == 0.0f) ? 1e-5f : gm;
    }
    if (threadIdx.x < NA * 6) sanch[threadIdx.x] = anchors[threadIdx.x];
    if (threadIdx.x < 2) scnt[threadIdx.x] = 0;
    __syncthreads();
    float iH = im_info[0], iW = im_info[1], iD = im_info[2];
    int lane = threadIdx.x & 31;

    for (int t = 0; t < 8; t++) {
        int i = base + t * 256 + threadIdx.x;
        int e = b * TOTAL + i;
        int a = i % NA; int q = i / NA;
        int d = q % ND; q /= ND;
        int w = q % NW; int h = q / NW;
        float shx = w * 16.0f, shy = h * 16.0f, shz = d * 16.0f;
        const float* an = sanch + a * 6;
        float ax1 = an[0] + shx, ay1 = an[1] + shy;
        float ax2 = an[2] + shx, ay2 = an[3] + shy;
        float az1 = an[4] + shz, az2 = an[5] + shz;
        bool inside = (ax1 >= 0.0f) && (ay1 >= 0.0f) && (az1 >= 0.0f) &&
                      (ax2 < iW) && (ay2 < iH) && (az2 < iD);
        signed char lab = -1;
        unsigned char am = 0;
        if (inside) {
            float aarea = f_area(ax1, ay1, ax2, ay2, az1, az2);
            float best = -1.0f;
            int bi = 0;
            bool tie = false;
#pragma unroll
            for (int k = 0; k < NK; k++) {
                float ov = f_ov(ax1, ay1, ax2, ay2, az1, az2, aarea, sgt + k * 7);
                if (ov > best) { best = ov; bi = k; }
                if (ov == sgm[k]) tie = true;
            }
            lab = (tie || best >= 0.7f) ? 1 : ((best < 0.3f) ? 0 : -1);
            am = (unsigned char)bi;
        }
        g_label[e] = lab;
        g_amax[e]  = am;

        unsigned b1 = __ballot_sync(0xFFFFFFFFu, lab == 1);
        unsigned b0 = __ballot_sync(0xFFFFFFFFu, lab == 0);
        if (lane == 0) {
            if (b1) atomicAdd(&scnt[0], __popc(b1));
            if (b0) atomicAdd(&scnt[1], __popc(b0));
        }
        if (lab == 1) {
            unsigned bin = __float_as_uint(rfg[e]) >> 16;
            atomicAdd(&g_hist[(b * 2) * NBINS + bin], 1u);
        } else if (lab == 0) {
            unsigned bin = __float_as_uint(rbg[e]) >> 16;
            atomicAdd(&g_hist[(b * 2 + 1) * NBINS + bin], 1u);
        }
    }
    __syncthreads();
    if (threadIdx.x < 2 && scnt[threadIdx.x]) atomicAdd(&g_cnt[b * 2 + threadIdx.x], scnt[threadIdx.x]);
}

// ---------------- radix-select update (one block per group) ----------------
__global__ void __launch_bounds__(1024) k_upd(int P) {
    int grp = blockIdx.x;
    int t   = threadIdx.x;      // scan order: t=0 is the TOP chunk
    int c   = 1023 - t;         // chunk of bins [c*64, c*64+63]
    unsigned* hist = g_hist + grp * NBINS;
    __shared__ unsigned ssum[1024];

    unsigned mysum = 0;
    for (int j = 0; j < 64; j++) mysum += hist[c * 64 + j];
    ssum[t] = mysum;
    __syncthreads();
    for (int off = 1; off < 1024; off <<= 1) {
        unsigned v = (t >= off) ? ssum[t - off] : 0u;
        __syncthreads();
        ssum[t] += v;
        __syncthreads();
    }
    unsigned total = ssum[1023];

    int m0;
    if (P == 0) {
        if ((grp & 1) == 0) m0 = NUMFG;
        else { int fgc = g_cnt[grp - 1]; int kept = (fgc < NUMFG) ? fgc : NUMFG; m0 = RPNB - kept; }
    } else {
        m0 = g_m[grp];
    }
    if (P == 0 && grp == 3 && t == 0) {
        int fg1 = g_cnt[2]; if (fg1 > NUMFG) fg1 = NUMFG;
        int cap = RPNB - fg1;
        int bg1 = g_cnt[3]; if (bg1 > cap) bg1 = cap;
        int ne = fg1 + bg1;
        g_wval = 1.0f / (float)(ne > 0 ? ne : 1);
    }

    if (g_act[grp]) {
        // keep-all only valid at pass 0 (group = whole candidate set).
        // At P>=1, m0 <= total is guaranteed; m0 == total means the threshold
        // is the minimum key of the current prefix group — keep recursing.
        if (P == 0 && (unsigned)m0 >= total) {
            if (t == 0) { g_act[grp] = 0; g_prefix[grp] = 0ULL; }
        } else {
            unsigned incl = ssum[t];
            unsigned excl = incl - mysum;
            if (excl < (unsigned)m0 && (unsigned)m0 <= incl) {
                unsigned acc = excl;
                int binsel = c * 64;
                for (int j = 63; j >= 0; j--) {
                    unsigned cc = hist[c * 64 + j];
                    if (acc + cc >= (unsigned)m0) { binsel = c * 64 + j; break; }
                    acc += cc;
                }
                g_prefix[grp] |= ((unsigned long long)(unsigned)binsel) << (48 - 16 * P);
                g_m[grp] = m0 - (int)acc;
            }
        }
    }
    __syncthreads();
    for (int j = 0; j < 64; j++) hist[c * 64 + j] = 0u;
}

// ---------------- histogram pass P (P = 1,2,3) ----------------
__global__ void __launch_bounds__(256) k_hist(int P, const float* __restrict__ rfg,
                                              const float* __restrict__ rbg) {
    int e = blockIdx.x * 256 + threadIdx.x;
    int lab = g_label[e];
    if (lab < 0) return;
    int b = (e >= TOTAL) ? 1 : 0;
    unsigned i = (unsigned)(e - b * TOTAL);
    int grp = b * 2 + (lab == 0 ? 1 : 0);
    if (!g_act[grp]) return;
    float rv = (lab == 1) ? rfg[e] : rbg[e];
    unsigned long long key = ((unsigned long long)__float_as_uint(rv) << 32) | (unsigned)(~i);
    int sh = 64 - 16 * P;
    if ((key >> sh) != (g_prefix[grp] >> sh)) return;
    unsigned bin = (unsigned)(key >> (sh - 16)) & 0xFFFFu;
    atomicAdd(&g_hist[grp * NBINS + bin], 1u);
}

// ---------------- final label resolution (coalesced anchor order) ----------------
__global__ void __launch_bounds__(256) k_final(const float* __restrict__ rfg,
                                               const float* __restrict__ rbg) {
    int e = blockIdx.x * 256 + threadIdx.x;
    int lab = g_label[e];
    signed char out = -1;
    if (lab >= 0) {
        int b = (e >= TOTAL) ? 1 : 0;
        unsigned i = (unsigned)(e - b * TOTAL);
        int grp = b * 2 + (lab == 0 ? 1 : 0);
        float rv = (lab == 1) ? rfg[e] : rbg[e];
        unsigned long long key = ((unsigned long long)__float_as_uint(rv) << 32) | (unsigned)(~i);
        if (key >= g_prefix[grp]) out = (signed char)lab;
    }
    g_flabel[e] = out;
}

// ---------------- passD: write all outputs, (b,a,h,w,d) order ----------------
__global__ void __launch_bounds__(256) k_passD(const float* __restrict__ anchors,
                                               const float* __restrict__ im_info,
                                               const float* __restrict__ gt,
                                               float* __restrict__ out) {
    int tid = blockIdx.x * 256 + threadIdx.x;
    int d = tid % ND; int q = tid / ND;
    int w = q % NW; q /= NW;
    int h = q % NH; q /= NH;
    int a = q % NA; int b = q / NA;
    int i = ((h * NW + w) * ND + d) * NA + a;
    int e = b * TOTAL + i;

    __shared__ float sanch[NA * 6];
    __shared__ float sgt[NB * NK * 6];
    if (threadIdx.x < NA * 6) sanch[threadIdx.x] = anchors[threadIdx.x];
    if (threadIdx.x < NB * NK) {
        const float* g = gt + threadIdx.x * 7;
        float* o = sgt + threadIdx.x * 6;
        o[0] = g[0]; o[1] = g[1]; o[2] = g[2]; o[3] = g[3]; o[4] = g[4]; o[5] = g[5];
    }
    __syncthreads();

    float shx = w * 16.0f, shy = h * 16.0f, shz = d * 16.0f;
    const float* an = sanch + a * 6;
    float ax1 = an[0] + shx, ay1 = an[1] + shy;
    float ax2 = an[2] + shx, ay2 = an[3] + shy;
    float az1 = an[4] + shz, az2 = an[5] + shz;
    float iH = im_info[0], iW = im_info[1], iD = im_info[2];
    bool inside = (ax1 >= 0.0f) && (ay1 >= 0.0f) && (az1 >= 0.0f) &&
                  (ax2 < iW) && (ay2 < iH) && (az2 < iD);

    int lab = (int)g_flabel[e];
    float t0 = 0.0f, t1 = 0.0f, t2 = 0.0f, t3 = 0.0f, t4 = 0.0f, t5 = 0.0f;
    if (inside) {
        int am = (int)g_amax[e];
        const float* g = sgt + (b * NK + am) * 6;
        float ew = ax2 - ax1 + 1.0f, eh = ay2 - ay1 + 1.0f, ed = az2 - az1 + 1.0f;
        float ecx = ax1 + 0.5f * (ew - 1.0f);
        float ecy = ay1 + 0.5f * (eh - 1.0f);
        float ecz = az1 + 0.5f * (ed - 1.0f);
        float gw = g[2] - g[0] + 1.0f, gh = g[3] - g[1] + 1.0f, gd = g[5] - g[4] + 1.0f;
        float gcx = g[0] + 0.5f * (gw - 1.0f);
        float gcy = g[1] + 0.5f * (gh - 1.0f);
        float gcz = g[4] + 0.5f * (gd - 1.0f);
        t0 = (gcx - ecx) / ew;
        t1 = (gcy - ecy) / eh;
        t2 = (gcz - ecz) / ed;
        t3 = logf(gw / ew);
        t4 = logf(gh / eh);
        t5 = logf(gd / ed);
    }

    float labf = (float)lab;
    float iwv  = (lab == 1) ? 1.0f : 0.0f;
    float owv  = (lab >= 0) ? g_wval : 0.0f;

    out[tid] = labf;  // labels region: exact (b,a,h,w,d) flat order

    long long pix  = (long long)(((h * NW + w) * ND) + d);
    long long base = (long long)(b * 54 + a * 6) * HWD + pix;
    float* bt = out + OFF_BT + base;
    bt[0 * HWD] = t0; bt[1 * HWD] = t1; bt[2 * HWD] = t2;
    bt[3 * HWD] = t3; bt[4 * HWD] = t4; bt[5 * HWD] = t5;
    float* iwp = out + OFF_IW + base;
    float* owp = out + OFF_OW + base;
#pragma unroll
    for (int cch = 0; cch < 6; cch++) { iwp[cch * HWD] = iwv; owp[cch * HWD] = owv; }
}

// ---------------- launch ----------------
extern "C" void kernel_launch(void* const* d_in, const int* in_sizes, int n_in,
                              void* d_out, int out_size) {
    const float* gt      = (const float*)d_in[1];
    const float* im_info = (const float*)d_in[2];
    const float* anchors = (const float*)d_in[4];
    const float* rfg     = (const float*)d_in[5];
    const float* rbg     = (const float*)d_in[6];
    float* out           = (float*)d_out;

    k_init<<<1024, 256>>>(gt);
    k_passA<<<NB * BPB, 256>>>(anchors, im_info);
    k_passB<<<NB * BPB, 256>>>(anchors, im_info, rfg, rbg);
    k_upd<<<4, 1024>>>(0);
    k_hist<<<(NB * TOTAL) / 256, 256>>>(1, rfg, rbg);
    k_upd<<<4, 1024>>>(1);
    k_hist<<<(NB * TOTAL) / 256, 256>>>(2, rfg, rbg);
    k_upd<<<4, 1024>>>(2);
    k_hist<<<(NB * TOTAL) / 256, 256>>>(3, rfg, rbg);
    k_upd<<<4, 1024>>>(3);
    k_final<<<(NB * TOTAL) / 256, 256>>>(rfg, rbg);
    k_passD<<<OUTTOT / 256, 256>>>(anchors, im_info, gt, out);
}

// round 4
// speedup vs baseline: 2.7579x; 2.7579x over previous
#include <cuda_runtime.h>
#include <cuda_bf16.h>
#include <stdint.h>

#define NB 2
#define NH 48
#define NW 48
#define ND 24
#define NA 9
#define NK 20
#define TOTAL  497664            // NH*NW*ND*NA
#define HWD    55296             // NH*NW*ND
#define OUTTOT 995328            // NB*NA*HWD
#define NUMFG 128
#define RPNB  256
#define NBINS 65536
#define BPB   243                // blocks per batch in pass A/B (2048 anchors each)
#define CAP   4096               // per-group candidate buffer (threshold bin members)

#define OFF_BT  995328
#define OFF_IW  (OFF_BT + 5971968)
#define OFF_OW  (OFF_IW + 5971968)

// ---------------- device scratch (no allocations allowed) ----------------
__device__ float              g_gt[NB * NK * 7];   // x1 y1 x2 y2 z1 z2 area
__device__ int                g_gtmax[NB * NK];    // float-as-int max IoU per gt
__device__ signed char        g_label[NB * TOTAL];
__device__ unsigned char      g_amax[NB * TOTAL];
__device__ int                g_cnt[4];            // [b*2 + isbg] candidate counts
__device__ unsigned int       g_hist[4 * NBINS];
__device__ unsigned int       g_bin[4];            // selected 16-bit bin per group
__device__ int                g_m[4];              // rank within selected bin (1-based)
__device__ int                g_act[4];            // 0 => keep all candidates
__device__ int                g_ncand[4];
__device__ unsigned long long g_cand[4 * CAP];
__device__ unsigned long long g_thresh[4];         // exact m-th largest key (0 => keep all)
__device__ float              g_wval;

// IoU with strict _rn intrinsics so passA and passB are bitwise identical.
__device__ __forceinline__ float f_ov(float ax1, float ay1, float ax2, float ay2,
                                      float az1, float az2, float aarea,
                                      const float* __restrict__ g) {
    float iw = __fadd_rn(__fsub_rn(fminf(ax2, g[2]), fmaxf(ax1, g[0])), 1.0f);
    if (iw <= 0.0f) return 0.0f;
    float ih = __fadd_rn(__fsub_rn(fminf(ay2, g[3]), fmaxf(ay1, g[1])), 1.0f);
    if (ih <= 0.0f) return 0.0f;
    float idp = __fadd_rn(__fsub_rn(fminf(az2, g[5]), fmaxf(az1, g[4])), 1.0f);
    if (idp <= 0.0f) return 0.0f;
    float inter = __fmul_rn(__fmul_rn(iw, ih), idp);
    float den   = __fsub_rn(__fadd_rn(aarea, g[6]), inter);
    return __fdiv_rn(inter, den);
}

__device__ __forceinline__ float f_area(float x1, float y1, float x2, float y2,
                                        float z1, float z2) {
    float aw = __fadd_rn(__fsub_rn(x2, x1), 1.0f);
    float ah = __fadd_rn(__fsub_rn(y2, y1), 1.0f);
    float ad = __fadd_rn(__fsub_rn(z2, z1), 1.0f);
    return __fmul_rn(__fmul_rn(aw, ah), ad);
}

// ---------------- k_init ----------------
__global__ void k_init(const float* __restrict__ gt) {
    int idx = blockIdx.x * blockDim.x + threadIdx.x;
    if (idx < 4 * NBINS) g_hist[idx] = 0u;
    if (idx < NB * NK) {
        g_gtmax[idx] = __float_as_int(-1.0f);
        const float* g = gt + idx * 7;
        float x1 = g[0], y1 = g[1], x2 = g[2], y2 = g[3], z1 = g[4], z2 = g[5];
        float gw = __fadd_rn(__fsub_rn(x2, x1), 1.0f);
        float gh = __fadd_rn(__fsub_rn(y2, y1), 1.0f);
        float gd = __fadd_rn(__fsub_rn(z2, z1), 1.0f);
        // zero-size gt => force ov = 0 via impossible box
        if (gw == 1.0f && gh == 1.0f && gd == 1.0f) { x2 = -1e9f; }
        float* o = g_gt + idx * 7;
        o[0] = x1; o[1] = y1; o[2] = x2; o[3] = y2; o[4] = z1; o[5] = z2;
        o[6] = __fmul_rn(__fmul_rn(gw, gh), gd);
    }
    if (idx < 4) { g_cnt[idx] = 0; g_m[idx] = 0; g_act[idx] = 1; g_ncand[idx] = 0; g_thresh[idx] = 0ULL; }
}

// ---------------- passA: gt_max over inside anchors ----------------
__global__ void __launch_bounds__(256) k_passA(const float* __restrict__ anchors,
                                               const float* __restrict__ im_info) {
    int b    = blockIdx.x / BPB;
    int base = (blockIdx.x % BPB) * 2048;
    __shared__ float sgt[NK * 7];
    __shared__ float sanch[NA * 6];
    __shared__ float red[8][NK];
    for (int j = threadIdx.x; j < NK * 7; j += 256) sgt[j] = g_gt[b * NK * 7 + j];
    if (threadIdx.x < NA * 6) sanch[threadIdx.x] = anchors[threadIdx.x];
    __syncthreads();
    float iH = im_info[0], iW = im_info[1], iD = im_info[2];

    float vmax[NK];
#pragma unroll
    for (int k = 0; k < NK; k++) vmax[k] = -1.0f;

    for (int t = 0; t < 8; t++) {
        int i = base + t * 256 + threadIdx.x;
        int a = i % NA; int q = i / NA;
        int d = q % ND; q /= ND;
        int w = q % NW; int h = q / NW;
        float shx = w * 16.0f, shy = h * 16.0f, shz = d * 16.0f;
        const float* an = sanch + a * 6;
        float ax1 = an[0] + shx, ay1 = an[1] + shy;
        float ax2 = an[2] + shx, ay2 = an[3] + shy;
        float az1 = an[4] + shz, az2 = an[5] + shz;
        bool inside = (ax1 >= 0.0f) && (ay1 >= 0.0f) && (az1 >= 0.0f) &&
                      (ax2 < iW) && (ay2 < iH) && (az2 < iD);
        if (!inside) continue;
        float aarea = f_area(ax1, ay1, ax2, ay2, az1, az2);
#pragma unroll
        for (int k = 0; k < NK; k++) {
            float ov = f_ov(ax1, ay1, ax2, ay2, az1, az2, aarea, sgt + k * 7);
            vmax[k] = fmaxf(vmax[k], ov);
        }
    }
    int lane = threadIdx.x & 31, wid = threadIdx.x >> 5;
#pragma unroll
    for (int k = 0; k < NK; k++) {
        float v = vmax[k];
#pragma unroll
        for (int off = 16; off; off >>= 1) v = fmaxf(v, __shfl_xor_sync(0xFFFFFFFFu, v, off));
        if (lane == 0) red[wid][k] = v;
    }
    __syncthreads();
    if (threadIdx.x < NK) {
        float m = red[0][threadIdx.x];
#pragma unroll
        for (int wq = 1; wq < 8; wq++) m = fmaxf(m, red[wq][threadIdx.x]);
        atomicMax(&g_gtmax[b * NK + threadIdx.x], __float_as_int(m));
    }
}

// ---------------- passB: labels, argmax, hist pass 0, counts ----------------
__global__ void __launch_bounds__(256) k_passB(const float* __restrict__ anchors,
                                               const float* __restrict__ im_info,
                                               const float* __restrict__ rfg,
                                               const float* __restrict__ rbg) {
    int b    = blockIdx.x / BPB;
    int base = (blockIdx.x % BPB) * 2048;
    __shared__ float sgt[NK * 7];
    __shared__ float sgm[NK];
    __shared__ float sanch[NA * 6];
    __shared__ int   scnt[2];
    for (int j = threadIdx.x; j < NK * 7; j += 256) sgt[j] = g_gt[b * NK * 7 + j];
    if (threadIdx.x < NK) {
        float gm = __int_as_float(g_gtmax[b * NK + threadIdx.x]);
        sgm[threadIdx.x] = (gm == 0.0f) ? 1e-5f : gm;
    }
    if (threadIdx.x < NA * 6) sanch[threadIdx.x] = anchors[threadIdx.x];
    if (threadIdx.x < 2) scnt[threadIdx.x] = 0;
    __syncthreads();
    float iH = im_info[0], iW = im_info[1], iD = im_info[2];
    int lane = threadIdx.x & 31;

    for (int t = 0; t < 8; t++) {
        int i = base + t * 256 + threadIdx.x;
        int e = b * TOTAL + i;
        int a = i % NA; int q = i / NA;
        int d = q % ND; q /= ND;
        int w = q % NW; int h = q / NW;
        float shx = w * 16.0f, shy = h * 16.0f, shz = d * 16.0f;
        const float* an = sanch + a * 6;
        float ax1 = an[0] + shx, ay1 = an[1] + shy;
        float ax2 = an[2] + shx, ay2 = an[3] + shy;
        float az1 = an[4] + shz, az2 = an[5] + shz;
        bool inside = (ax1 >= 0.0f) && (ay1 >= 0.0f) && (az1 >= 0.0f) &&
                      (ax2 < iW) && (ay2 < iH) && (az2 < iD);
        signed char lab = -1;
        unsigned char am = 0;
        if (inside) {
            float aarea = f_area(ax1, ay1, ax2, ay2, az1, az2);
            float best = -1.0f;
            int bi = 0;
            bool tie = false;
#pragma unroll
            for (int k = 0; k < NK; k++) {
                float ov = f_ov(ax1, ay1, ax2, ay2, az1, az2, aarea, sgt + k * 7);
                if (ov > best) { best = ov; bi = k; }
                if (ov == sgm[k]) tie = true;
            }
            lab = (tie || best >= 0.7f) ? 1 : ((best < 0.3f) ? 0 : -1);
            am = (unsigned char)bi;
        }
        g_label[e] = lab;
        g_amax[e]  = am;

        unsigned b1 = __ballot_sync(0xFFFFFFFFu, lab == 1);
        unsigned b0 = __ballot_sync(0xFFFFFFFFu, lab == 0);
        if (lane == 0) {
            if (b1) atomicAdd(&scnt[0], __popc(b1));
            if (b0) atomicAdd(&scnt[1], __popc(b0));
        }
        if (lab == 1) {
            unsigned bin = __float_as_uint(rfg[e]) >> 16;
            atomicAdd(&g_hist[(b * 2) * NBINS + bin], 1u);
        } else if (lab == 0) {
            unsigned bin = __float_as_uint(rbg[e]) >> 16;
            atomicAdd(&g_hist[(b * 2 + 1) * NBINS + bin], 1u);
        }
    }
    __syncthreads();
    if (threadIdx.x < 2 && scnt[threadIdx.x]) atomicAdd(&g_cnt[b * 2 + threadIdx.x], scnt[threadIdx.x]);
}

// ---------------- upd0: find threshold bin per group (single pass) ----------------
__global__ void __launch_bounds__(1024) k_upd0() {
    int grp = blockIdx.x;
    int t   = threadIdx.x;      // t=0 owns the TOP chunk
    int c   = 1023 - t;         // chunk of bins [c*64, c*64+63]
    const unsigned* hist = g_hist + grp * NBINS;
    int lane = t & 31, wid = t >> 5;
    __shared__ unsigned wtot[32];
    __shared__ unsigned woff[32];

    // vectorized chunk sum: 16 x uint4 (256B contiguous per thread)
    const uint4* hp = (const uint4*)(hist + c * 64);
    unsigned mysum = 0;
#pragma unroll
    for (int j = 0; j < 16; j++) {
        uint4 v = hp[j];
        mysum += v.x + v.y + v.z + v.w;
    }
    // warp inclusive scan in t-order
    unsigned incl = mysum;
#pragma unroll
    for (int off = 1; off < 32; off <<= 1) {
        unsigned u = __shfl_up_sync(0xFFFFFFFFu, incl, off);
        if (lane >= off) incl += u;
    }
    if (lane == 31) wtot[wid] = incl;
    __syncthreads();
    if (wid == 0) {
        unsigned s = wtot[lane];
#pragma unroll
        for (int off = 1; off < 32; off <<= 1) {
            unsigned u = __shfl_up_sync(0xFFFFFFFFu, s, off);
            if (lane >= off) s += u;
        }
        woff[lane] = s;
    }
    __syncthreads();
    if (wid > 0) incl += woff[wid - 1];
    unsigned total = woff[31];

    int m0;
    if ((grp & 1) == 0) m0 = NUMFG;
    else { int fgc = g_cnt[grp - 1]; int kept = (fgc < NUMFG) ? fgc : NUMFG; m0 = RPNB - kept; }

    if (grp == 3 && t == 0) {
        int fg1 = g_cnt[2]; if (fg1 > NUMFG) fg1 = NUMFG;
        int cap = RPNB - fg1;
        int bg1 = g_cnt[3]; if (bg1 > cap) bg1 = cap;
        int ne = fg1 + bg1;
        g_wval = 1.0f / (float)(ne > 0 ? ne : 1);
    }

    if ((unsigned)m0 >= total) {
        if (t == 0) { g_act[grp] = 0; g_thresh[grp] = 0ULL; }
    } else {
        unsigned excl = incl - mysum;
        if (excl < (unsigned)m0 && (unsigned)m0 <= incl) {
            unsigned acc = excl;
            int binsel = c * 64;
            for (int j = 63; j >= 0; j--) {
                unsigned cc = hist[c * 64 + j];
                if (acc + cc >= (unsigned)m0) { binsel = c * 64 + j; break; }
                acc += cc;
            }
            g_bin[grp] = (unsigned)binsel;
            g_m[grp]   = m0 - (int)acc;   // 1-based rank within bin
        }
    }
}

// ---------------- collect: gather keys in the threshold bin ----------------
__global__ void __launch_bounds__(256) k_collect(const float* __restrict__ rfg,
                                                 const float* __restrict__ rbg) {
    int e = blockIdx.x * 256 + threadIdx.x;
    int lab = g_label[e];
    if (lab < 0) return;
    int b = (e >= TOTAL) ? 1 : 0;
    unsigned i = (unsigned)(e - b * TOTAL);
    int grp = b * 2 + (lab == 0 ? 1 : 0);
    if (!g_act[grp]) return;
    float rv = (lab == 1) ? rfg[e] : rbg[e];
    unsigned rb = __float_as_uint(rv);
    if ((rb >> 16) != g_bin[grp]) return;
    unsigned long long key = ((unsigned long long)rb << 32) | (unsigned)(~i);
    int pos = atomicAdd(&g_ncand[grp], 1);
    if (pos < CAP) g_cand[grp * CAP + pos] = key;
}

// ---------------- finish: exact m-th largest within the bin ----------------
__global__ void __launch_bounds__(256) k_finish() {
    int grp = blockIdx.x;
    if (!g_act[grp]) return;      // thresh already 0
    __shared__ unsigned long long sk[CAP];
    int n = g_ncand[grp];
    if (n > CAP) n = CAP;
    int m = g_m[grp];             // 1-based rank
    for (int i = threadIdx.x; i < n; i += 256) sk[i] = g_cand[grp * CAP + i];
    __syncthreads();
    for (int i = threadIdx.x; i < n; i += 256) {
        unsigned long long k = sk[i];
        int cg = 0;
        for (int j = 0; j < n; j++) cg += (sk[j] > k) ? 1 : 0;
        if (cg == m - 1) g_thresh[grp] = k;
    }
}

// ---------------- passD: final labels + all outputs, (b,a,h,w,d) order ----------------
__global__ void __launch_bounds__(256) k_passD(const float* __restrict__ anchors,
                                               const float* __restrict__ im_info,
                                               const float* __restrict__ gt,
                                               const float* __restrict__ rfg,
                                               const float* __restrict__ rbg,
                                               float* __restrict__ out) {
    int tid = blockIdx.x * 256 + threadIdx.x;
    int d = tid % ND; int q = tid / ND;
    int w = q % NW; q /= NW;
    int h = q % NH; q /= NH;
    int a = q % NA; int b = q / NA;
    int i = ((h * NW + w) * ND + d) * NA + a;
    int e = b * TOTAL + i;

    __shared__ float sanch[NA * 6];
    __shared__ float sgt[NB * NK * 6];
    __shared__ unsigned long long sth[4];
    if (threadIdx.x < NA * 6) sanch[threadIdx.x] = anchors[threadIdx.x];
    if (threadIdx.x < NB * NK) {
        const float* g = gt + threadIdx.x * 7;
        float* o = sgt + threadIdx.x * 6;
        o[0] = g[0]; o[1] = g[1]; o[2] = g[2]; o[3] = g[3]; o[4] = g[4]; o[5] = g[5];
    }
    if (threadIdx.x < 4) sth[threadIdx.x] = g_thresh[threadIdx.x];
    __syncthreads();

    float shx = w * 16.0f, shy = h * 16.0f, shz = d * 16.0f;
    const float* an = sanch + a * 6;
    float ax1 = an[0] + shx, ay1 = an[1] + shy;
    float ax2 = an[2] + shx, ay2 = an[3] + shy;
    float az1 = an[4] + shz, az2 = an[5] + shz;
    float iH = im_info[0], iW = im_info[1], iD = im_info[2];
    bool inside = (ax1 >= 0.0f) && (ay1 >= 0.0f) && (az1 >= 0.0f) &&
                  (ax2 < iW) && (ay2 < iH) && (az2 < iD);

    // final label: candidates kept iff key >= group threshold
    int lab = (int)g_label[e];
    if (lab >= 0) {
        int grp = b * 2 + (lab == 0 ? 1 : 0);
        float rv = (lab == 1) ? rfg[e] : rbg[e];
        unsigned long long key = ((unsigned long long)__float_as_uint(rv) << 32) | (unsigned)(~(unsigned)i);
        if (key < sth[grp]) lab = -1;
    }

    float t0 = 0.0f, t1 = 0.0f, t2 = 0.0f, t3 = 0.0f, t4 = 0.0f, t5 = 0.0f;
    if (inside) {
        int am = (int)g_amax[e];
        const float* g = sgt + (b * NK + am) * 6;
        float ew = ax2 - ax1 + 1.0f, eh = ay2 - ay1 + 1.0f, ed = az2 - az1 + 1.0f;
        float ecx = ax1 + 0.5f * (ew - 1.0f);
        float ecy = ay1 + 0.5f * (eh - 1.0f);
        float ecz = az1 + 0.5f * (ed - 1.0f);
        float gw = g[2] - g[0] + 1.0f, gh = g[3] - g[1] + 1.0f, gd = g[5] - g[4] + 1.0f;
        float gcx = g[0] + 0.5f * (gw - 1.0f);
        float gcy = g[1] + 0.5f * (gh - 1.0f);
        float gcz = g[4] + 0.5f * (gd - 1.0f);
        t0 = (gcx - ecx) / ew;
        t1 = (gcy - ecy) / eh;
        t2 = (gcz - ecz) / ed;
        t3 = logf(gw / ew);
        t4 = logf(gh / eh);
        t5 = logf(gd / ed);
    }

    float labf = (float)lab;
    float iwv  = (lab == 1) ? 1.0f : 0.0f;
    float owv  = (lab >= 0) ? g_wval : 0.0f;

    out[tid] = labf;  // labels region: exact (b,a,h,w,d) flat order

    long long pix  = (long long)(((h * NW + w) * ND) + d);
    long long base = (long long)(b * 54 + a * 6) * HWD + pix;
    float* bt = out + OFF_BT + base;
    bt[0 * HWD] = t0; bt[1 * HWD] = t1; bt[2 * HWD] = t2;
    bt[3 * HWD] = t3; bt[4 * HWD] = t4; bt[5 * HWD] = t5;
    float* iwp = out + OFF_IW + base;
    float* owp = out + OFF_OW + base;
#pragma unroll
    for (int cch = 0; cch < 6; cch++) { iwp[cch * HWD] = iwv; owp[cch * HWD] = owv; }
}

// ---------------- launch ----------------
extern "C" void kernel_launch(void* const* d_in, const int* in_sizes, int n_in,
                              void* d_out, int out_size) {
    const float* gt      = (const float*)d_in[1];
    const float* im_info = (const float*)d_in[2];
    const float* anchors = (const float*)d_in[4];
    const float* rfg     = (const float*)d_in[5];
    const float* rbg     = (const float*)d_in[6];
    float* out           = (float*)d_out;

    k_init<<<1024, 256>>>(gt);
    k_passA<<<NB * BPB, 256>>>(anchors, im_info);
    k_passB<<<NB * BPB, 256>>>(anchors, im_info, rfg, rbg);
    k_upd0<<<4, 1024>>>();
    k_collect<<<(NB * TOTAL) / 256, 256>>>(rfg, rbg);
    k_finish<<<4, 256>>>();
    k_passD<<<OUTTOT / 256, 256>>>(anchors, im_info, gt, rfg, rbg, out);
}